// round 16
// baseline (speedup 1.0000x reference)
#include <cuda_runtime.h>
#include <cuda_bf16.h>
#include <cstdint>
#include <math.h>

// ---------------------------------------------------------------------------
// Attention block, bf16 mma.sync pipeline.
// R16: bilinear fold — M = Wq^T Wk precomputed; y = M x replaces q AND k.
//      e_ij = x_i.y_j + w_i + u_j + c0 (bias-exact). PDL chain throughout.
// B=16, C=512, HW=1024, 32 groups, eps=1e-6
// ---------------------------------------------------------------------------

#define B_ 16
#define C_ 512
#define HW_ 1024
#define NG_ 32

__device__ __nv_bfloat16 g_xnt[(long long)B_ * HW_ * C_];
__device__ __nv_bfloat16 g_yt [(long long)B_ * HW_ * C_];
__device__ __nv_bfloat16 g_v  [(long long)B_ * C_ * HW_];
__device__ __nv_bfloat16 g_at [(long long)B_ * HW_ * HW_];   // exp(e), unnormalized
__device__ __nv_bfloat16 g_ot [(long long)B_ * HW_ * C_];
__device__ __nv_bfloat16 g_wv[C_ * C_], g_wp[C_ * C_];
__device__ __nv_bfloat16 g_wqt[C_ * C_], g_wkt[C_ * C_];      // transposed wq, wk
__device__ __nv_bfloat16 g_m[C_ * C_];                        // M[c,c'] = sum_o Wq[o,c] Wk[o,c']

// fp32 accumulators: [rsum 16384][w 16384][u 16384][pvec 512][qvec 512][c0 1]
#define OFF_RS 0
#define OFF_W  16384
#define OFF_U  32768
#define OFF_PV 49152
#define OFF_QV 49664
#define OFF_C0 50176
__device__ float g_f[50184];

__inline__ __device__ float warp_sum(float v) {
    #pragma unroll
    for (int o = 16; o > 0; o >>= 1) v += __shfl_xor_sync(0xffffffffu, v, o);
    return v;
}
__device__ __forceinline__ uint32_t smem_u32(const void* p) {
    uint32_t a;
    asm("{ .reg .u64 t; cvta.to.shared.u64 t, %1; cvt.u32.u64 %0, t; }"
        : "=r"(a) : "l"(p));
    return a;
}
__device__ __forceinline__ void gdc_launch() {
    asm volatile("griddepcontrol.launch_dependents;");
}
__device__ __forceinline__ void gdc_wait() {
    asm volatile("griddepcontrol.wait;" ::: "memory");
}

#define CPA16(dst, src) \
    asm volatile("cp.async.cg.shared.global [%0], [%1], 16;" :: "r"(dst), "l"(src))
#define CPA_COMMIT() asm volatile("cp.async.commit_group;" ::: "memory")

#define LDSM4(R0, R1, R2, R3, addr) \
    asm volatile("ldmatrix.sync.aligned.m8n8.x4.shared.b16 {%0,%1,%2,%3}, [%4];" \
                 : "=r"(R0), "=r"(R1), "=r"(R2), "=r"(R3) : "r"(addr))

__device__ __forceinline__ void mma_bf16(float c[4], const uint32_t a[4],
                                         uint32_t b0, uint32_t b1) {
    asm volatile(
        "mma.sync.aligned.m16n8k16.row.col.f32.bf16.bf16.f32 "
        "{%0,%1,%2,%3}, {%4,%5,%6,%7}, {%8,%9}, {%0,%1,%2,%3};"
        : "+f"(c[0]), "+f"(c[1]), "+f"(c[2]), "+f"(c[3])
        : "r"(a[0]), "r"(a[1]), "r"(a[2]), "r"(a[3]), "r"(b0), "r"(b1));
}

// ---------------------------------------------------------------------------
// GEMM tiling constants (frozen config)
// ---------------------------------------------------------------------------
#define BK 64
#define ROWE 72
#define STGE (128 * ROWE)
#define NSTAGE 3
#define SMEM_BYTES (2 * NSTAGE * STGE * 2)

__device__ __forceinline__ void fill_stage(
    uint32_t abase, uint32_t bbase,
    const __nv_bfloat16* Ap, const __nv_bfloat16* Bp,
    int m0, int n0, int ldA, int ldB, int k0, int tid)
{
    #pragma unroll
    for (int i = 0; i < 4; i++) {
        int task = tid + i * 256;
        int row = task >> 3, kc = task & 7;
        CPA16(abase + (row * ROWE + kc * 8) * 2,
              Ap + (long long)(m0 + row) * ldA + k0 + kc * 8);
        CPA16(bbase + (row * ROWE + kc * 8) * 2,
              Bp + (long long)(n0 + row) * ldB + k0 + kc * 8);
    }
}

__device__ __forceinline__ void compute_chunk(
    float acc[2][8][4], uint32_t ab, uint32_t bb,
    int a_row, int a_koff, int b_row, int b_koff)
{
    #pragma unroll
    for (int ks = 0; ks < BK; ks += 16) {
        uint32_t afr[2][4];
        #pragma unroll
        for (int mi = 0; mi < 2; mi++) {
            uint32_t addr = ab + (((a_row + mi * 16) * ROWE) + ks + a_koff) * 2;
            LDSM4(afr[mi][0], afr[mi][1], afr[mi][2], afr[mi][3], addr);
        }
        uint32_t bcur[4], bnxt[4];
        {
            uint32_t addr = bb + ((b_row * ROWE) + ks + b_koff) * 2;
            LDSM4(bcur[0], bcur[1], bcur[2], bcur[3], addr);
        }
        #pragma unroll
        for (int np = 0; np < 4; np++) {
            if (np < 3) {
                uint32_t addr = bb +
                    (((b_row + (np + 1) * 16) * ROWE) + ks + b_koff) * 2;
                LDSM4(bnxt[0], bnxt[1], bnxt[2], bnxt[3], addr);
            }
            mma_bf16(acc[0][np * 2],     afr[0], bcur[0], bcur[1]);
            mma_bf16(acc[1][np * 2],     afr[1], bcur[0], bcur[1]);
            mma_bf16(acc[0][np * 2 + 1], afr[0], bcur[2], bcur[3]);
            mma_bf16(acc[1][np * 2 + 1], afr[1], bcur[2], bcur[3]);
            #pragma unroll
            for (int j = 0; j < 4; j++) bcur[j] = bnxt[j];
        }
    }
}

// ---------------------------------------------------------------------------
// Prep: weight conversion (wv, wp direct; wq, wk transposed) + bias vectors
//   pvec[c] = sum_o Wq[o,c] * bk[o]
//   qvec[c] = sum_o Wk[o,c] * bq[o]
//   c0 = dot(bq, bk)
// grid 641 x 512 threads.
// ---------------------------------------------------------------------------
__global__ __launch_bounds__(512) void prep_kernel(
    const float* __restrict__ wq, const float* __restrict__ wk,
    const float* __restrict__ wv, const float* __restrict__ wp,
    const float* __restrict__ bq, const float* __restrict__ bk)
{
    int bx = blockIdx.x, tid = threadIdx.x;
    gdc_launch();
    gdc_wait();   // after memset

    if (bx < 512) {
        int idx = bx * 2048 + tid * 4;
        int m = idx >> 18;
        int off = idx & 0x3FFFF;
        const float* src = (m == 0) ? wq : (m == 1) ? wk : (m == 2) ? wv : wp;
        float4 v4 = *reinterpret_cast<const float4*>(&src[off]);
        __nv_bfloat16 h[4] = {
            __float2bfloat16_rn(v4.x), __float2bfloat16_rn(v4.y),
            __float2bfloat16_rn(v4.z), __float2bfloat16_rn(v4.w)};
        if (m >= 2) {
            __nv_bfloat16* dst = (m == 2) ? g_wv : g_wp;
            *reinterpret_cast<__nv_bfloat162*>(&dst[off])     = __nv_bfloat162(h[0], h[1]);
            *reinterpret_cast<__nv_bfloat162*>(&dst[off + 2]) = __nv_bfloat162(h[2], h[3]);
        } else {
            // transpose: off = o*512 + c, 4 consecutive c, same o
            __nv_bfloat16* dt = (m == 0) ? g_wqt : g_wkt;
            int o = off >> 9, c = off & 511;
            #pragma unroll
            for (int j = 0; j < 4; j++) dt[(c + j) * C_ + o] = h[j];
        }
    } else if (bx < 640) {
        int bi = bx - 512;
        int which = bi >> 6;              // 0: pvec (Wq, bk), 1: qvec (Wk, bq)
        int r0 = (bi & 63) * 8;
        const float* W  = which ? wk : wq;
        const float* bv = which ? bq : bk;
        float* dst = which ? &g_f[OFF_QV] : &g_f[OFF_PV];
        float part = 0.f;
        #pragma unroll
        for (int o = 0; o < 8; o++) part += W[(r0 + o) * C_ + tid] * bv[r0 + o];
        atomicAdd(&dst[tid], part);
    } else {
        float p = bq[tid] * bk[tid];
        p = warp_sum(p);
        __shared__ float sh[16];
        if ((tid & 31) == 0) sh[tid >> 5] = p;
        __syncthreads();
        if (tid < 32) {
            float a = (tid < 16) ? sh[tid] : 0.f;
            a = warp_sum(a);
            if (tid == 0) g_f[OFF_C0] = a;
        }
    }
}

// ---------------------------------------------------------------------------
// GroupNorm: 512 threads, single global read; also accumulates
//   w[b,i] += sum_c xn*pvec ; u[b,i] += sum_c xn*qvec  (atomics)
// ---------------------------------------------------------------------------
__global__ __launch_bounds__(512) void gn_t_kernel(
    const float* __restrict__ x,
    const float* __restrict__ gamma,
    const float* __restrict__ beta)
{
    extern __shared__ float sd[];
    const int GSZ = 16 * HW_;
    int bg = blockIdx.x;
    int b = bg >> 5, g = bg & 31;
    long long base = (long long)bg * GSZ;
    int tid = threadIdx.x;

    gdc_launch();
    gdc_wait();   // prep's pvec/qvec must be final

    float s = 0.f, sq = 0.f;
    #pragma unroll
    for (int e = tid * 4; e < GSZ; e += 512 * 4) {
        float4 v4 = *reinterpret_cast<const float4*>(&x[base + e]);
        *reinterpret_cast<float4*>(&sd[e]) = v4;
        s  += v4.x + v4.y + v4.z + v4.w;
        sq += v4.x * v4.x + v4.y * v4.y + v4.z * v4.z + v4.w * v4.w;
    }
    __shared__ float shs[16], shq[16];
    s = warp_sum(s); sq = warp_sum(sq);
    int wid = tid >> 5, lid = tid & 31;
    if (lid == 0) { shs[wid] = s; shq[wid] = sq; }
    __syncthreads();
    if (wid == 0) {
        float a = (lid < 16) ? shs[lid] : 0.f;
        float bb = (lid < 16) ? shq[lid] : 0.f;
        a = warp_sum(a); bb = warp_sum(bb);
        if (lid == 0) { shs[0] = a; shq[0] = bb; }
    }
    __syncthreads();
    float mean = shs[0] / (float)GSZ;
    float var  = shq[0] / (float)GSZ - mean * mean;
    float inv  = rsqrtf(var + 1e-6f);

    float ga[16], be[16], pv[16], qv[16];
    #pragma unroll
    for (int c = 0; c < 16; c++) {
        ga[c] = gamma[g * 16 + c] * inv;
        be[c] = beta[g * 16 + c] - mean * ga[c];
        pv[c] = g_f[OFF_PV + g * 16 + c];
        qv[c] = g_f[OFF_QV + g * 16 + c];
    }

    #pragma unroll
    for (int s0 = 0; s0 < HW_; s0 += 512) {
        int sp = s0 + tid;
        union { __nv_bfloat16 h[16]; uint4 u[2]; } o;
        float wacc = 0.f, uacc = 0.f;
        #pragma unroll
        for (int c = 0; c < 16; c++) {
            float xv = sd[c * HW_ + sp] * ga[c] + be[c];
            o.h[c] = __float2bfloat16_rn(xv);
            wacc += xv * pv[c];
            uacc += xv * qv[c];
        }
        atomicAdd(&g_f[OFF_W + b * HW_ + sp], wacc);
        atomicAdd(&g_f[OFF_U + b * HW_ + sp], uacc);
        uint4* dst = reinterpret_cast<uint4*>(
            &g_xnt[((long long)b * HW_ + sp) * C_ + g * 16]);
        dst[0] = o.u[0];
        dst[1] = o.u[1];
    }
}
#define GN_SMEM (16 * HW_ * 4)

// ---------------------------------------------------------------------------
// Fused y / v GEMM. grid (32, 1, 32):
//   z in [0,16):  y_t[j,c] = sum_c' xn_t[j,c'] * M[c,c']     (no bias)
//   z in [16,32): v[c,s]   = sum_c' wv[c,c'] * xn_t[s,c'] + bv[c]
// ---------------------------------------------------------------------------
__global__ __launch_bounds__(256, 2) void yv_gemm(const float* __restrict__ bv)
{
    extern __shared__ __nv_bfloat16 dsm[];

    int tid = threadIdx.x, wid = tid >> 5, lane = tid & 31;
    int g = lane >> 2, t = lane & 3;
    int wm = (wid & 3) * 32;
    int wn = (wid >> 2) * 64;

    const long long sSC = (long long)HW_ * C_;
    int zz = blockIdx.z;
    int xx = blockIdx.x;

    gdc_launch();

    const __nv_bfloat16 *Ap, *Bp;
    __nv_bfloat16* Co;
    int m0, n0, Nn;
    bool vmode;
    if (zz < 16) {
        int b = zz;
        Ap = g_xnt + (long long)b * sSC;
        Bp = g_m;
        Co = g_yt + (long long)b * sSC;
        m0 = (xx >> 2) * 128;
        n0 = (xx & 3) * 128;
        Nn = C_;
        vmode = false;
    } else {
        int b = zz - 16;
        Ap = g_wv;
        Bp = g_xnt + (long long)b * sSC;
        Co = g_v + (long long)b * sSC;
        m0 = (xx >> 3) * 128;
        n0 = (xx & 7) * 128;
        Nn = HW_;
        vmode = true;
    }

    uint32_t as_base = smem_u32(dsm);
    uint32_t bs_base = as_base + NSTAGE * STGE * 2;

    int a_row = wm + (lane & 15);
    int a_koff = (lane >> 4) * 8;
    int b_row = wn + ((lane >> 4) << 3) + (lane & 7);
    int b_koff = ((lane >> 3) & 1) * 8;

    float acc[2][8][4];
    #pragma unroll
    for (int a = 0; a < 2; a++)
        #pragma unroll
        for (int b2 = 0; b2 < 8; b2++)
            #pragma unroll
            for (int c = 0; c < 4; c++) acc[a][b2][c] = 0.f;

    const int nt = C_ / BK;

    gdc_wait();

    #pragma unroll
    for (int s = 0; s < NSTAGE - 1; s++) {
        fill_stage(as_base + s * STGE * 2, bs_base + s * STGE * 2,
                   Ap, Bp, m0, n0, C_, C_, s * BK, tid);
        CPA_COMMIT();
    }
    asm volatile("cp.async.wait_group %0;" :: "n"(NSTAGE - 2) : "memory");
    __syncthreads();

    for (int tt = 0; tt < nt; tt++) {
        int fs = tt + NSTAGE - 1;
        if (fs < nt) {
            int st = fs % NSTAGE;
            fill_stage(as_base + st * STGE * 2, bs_base + st * STGE * 2,
                       Ap, Bp, m0, n0, C_, C_, fs * BK, tid);
            CPA_COMMIT();
        }

        int cs = tt % NSTAGE;
        compute_chunk(acc, as_base + cs * STGE * 2, bs_base + cs * STGE * 2,
                      a_row, a_koff, b_row, b_koff);

        if (fs < nt)
            asm volatile("cp.async.wait_group %0;" :: "n"(NSTAGE - 2) : "memory");
        else
            asm volatile("cp.async.wait_group 0;" ::: "memory");
        __syncthreads();
    }

    #pragma unroll
    for (int mi = 0; mi < 2; mi++) {
        int mlo = m0 + wm + mi * 16 + g;
        int mhi = mlo + 8;
        float bmlo = vmode ? bv[mlo] : 0.f;
        float bmhi = vmode ? bv[mhi] : 0.f;
        #pragma unroll
        for (int ni = 0; ni < 8; ni++) {
            int col = n0 + wn + ni * 8 + 2 * t;
            float v00 = acc[mi][ni][0] + bmlo;
            float v01 = acc[mi][ni][1] + bmlo;
            float v10 = acc[mi][ni][2] + bmhi;
            float v11 = acc[mi][ni][3] + bmhi;
            long long olo = (long long)mlo * Nn + col;
            long long ohi = (long long)mhi * Nn + col;
            __nv_bfloat162 plo(__float2bfloat16_rn(v00), __float2bfloat16_rn(v01));
            __nv_bfloat162 phi(__float2bfloat16_rn(v10), __float2bfloat16_rn(v11));
            *reinterpret_cast<__nv_bfloat162*>(&Co[olo]) = plo;
            *reinterpret_cast<__nv_bfloat162*>(&Co[ohi]) = phi;
        }
    }
}

// ---------------------------------------------------------------------------
// Generic bf16 GEMM.
// HAS_EXP: val = exp(acc*alpha [+ alpha*(w[m]+u[n]+c0) if HAS_WU]),
//          bf16 out, atomic rowsum.
// HAS_RSC: val = acc / rowsum[m], bf16 out.
// BIAS_MODE=1 + HAS_RES: fp32 out (proj).
// ---------------------------------------------------------------------------
template<int BIAS_MODE, bool HAS_RES, bool OUT_BF16, bool HAS_EXP, bool HAS_RSC,
         bool HAS_WU>
__global__ __launch_bounds__(256, 2) void bf_gemm(
    const __nv_bfloat16* __restrict__ A, const __nv_bfloat16* __restrict__ Bm,
    void* __restrict__ Cv, const float* __restrict__ bias,
    const float* __restrict__ resid, const float* __restrict__ rowsc,
    float* __restrict__ rowsum_out,
    const float* __restrict__ wvec, const float* __restrict__ uvec,
    const float* __restrict__ c0p,
    int K, int ldA, int ldB, int N, float alpha,
    long long sA, long long sB, long long sC, long long sR)
{
    extern __shared__ __nv_bfloat16 dsm[];

    int tid = threadIdx.x, wid = tid >> 5, lane = tid & 31;
    int g = lane >> 2, t = lane & 3;
    int wm = (wid & 3) * 32;
    int wn = (wid >> 2) * 64;
    int n0 = blockIdx.x * 128;
    int m0 = blockIdx.y * 128;
    int bz = blockIdx.z;

    gdc_launch();

    const __nv_bfloat16* Ap = A  + (long long)bz * sA;
    const __nv_bfloat16* Bp = Bm + (long long)bz * sB;

    uint32_t as_base = smem_u32(dsm);
    uint32_t bs_base = as_base + NSTAGE * STGE * 2;

    int a_row = wm + (lane & 15);
    int a_koff = (lane >> 4) * 8;
    int b_row = wn + ((lane >> 4) << 3) + (lane & 7);
    int b_koff = ((lane >> 3) & 1) * 8;

    float acc[2][8][4];
    #pragma unroll
    for (int a = 0; a < 2; a++)
        #pragma unroll
        for (int b = 0; b < 8; b++)
            #pragma unroll
            for (int c = 0; c < 4; c++) acc[a][b][c] = 0.f;

    int nt = K / BK;

    gdc_wait();

    #pragma unroll
    for (int s = 0; s < NSTAGE - 1; s++) {
        fill_stage(as_base + s * STGE * 2, bs_base + s * STGE * 2,
                   Ap, Bp, m0, n0, ldA, ldB, s * BK, tid);
        CPA_COMMIT();
    }
    asm volatile("cp.async.wait_group %0;" :: "n"(NSTAGE - 2) : "memory");
    __syncthreads();

    for (int tt = 0; tt < nt; tt++) {
        int fs = tt + NSTAGE - 1;
        if (fs < nt) {
            int st = fs % NSTAGE;
            fill_stage(as_base + st * STGE * 2, bs_base + st * STGE * 2,
                       Ap, Bp, m0, n0, ldA, ldB, fs * BK, tid);
            CPA_COMMIT();
        }

        int cs = tt % NSTAGE;
        compute_chunk(acc, as_base + cs * STGE * 2, bs_base + cs * STGE * 2,
                      a_row, a_koff, b_row, b_koff);

        if (fs < nt)
            asm volatile("cp.async.wait_group %0;" :: "n"(NSTAGE - 2) : "memory");
        else
            asm volatile("cp.async.wait_group 0;" ::: "memory");
        __syncthreads();
    }

    const float* Rp = HAS_RES ? (resid + (long long)bz * sC) : nullptr;
    const float* Sp = HAS_RSC ? (rowsc + (long long)bz * sR) : nullptr;
    float* So = HAS_EXP ? (rowsum_out + (long long)bz * sR) : nullptr;
    const float* Wp = HAS_WU ? (wvec + (long long)bz * sR) : nullptr;
    const float* Up = HAS_WU ? (uvec + (long long)bz * sR) : nullptr;
    float c0v = HAS_WU ? c0p[0] : 0.f;
    float* Cf = OUT_BF16 ? nullptr : ((float*)Cv + (long long)bz * sC);
    __nv_bfloat16* Ch = OUT_BF16 ? ((__nv_bfloat16*)Cv + (long long)bz * sC) : nullptr;

    #pragma unroll
    for (int mi = 0; mi < 2; mi++) {
        int mlo = m0 + wm + mi * 16 + g;
        int mhi = mlo + 8;
        float bmlo = (BIAS_MODE == 1) ? bias[mlo] : 0.f;
        float bmhi = (BIAS_MODE == 1) ? bias[mhi] : 0.f;
        float rlo = HAS_RSC ? (1.0f / Sp[mlo]) : 1.f;
        float rhi = HAS_RSC ? (1.0f / Sp[mhi]) : 1.f;
        float wlo = HAS_WU ? alpha * (Wp[mlo] + c0v) : 0.f;
        float whi = HAS_WU ? alpha * (Wp[mhi] + c0v) : 0.f;
        float slo = 0.f, shi = 0.f;
        #pragma unroll
        for (int ni = 0; ni < 8; ni++) {
            int col = n0 + wn + ni * 8 + 2 * t;
            float u0 = HAS_WU ? alpha * Up[col]     : 0.f;
            float u1 = HAS_WU ? alpha * Up[col + 1] : 0.f;
            float v00 = acc[mi][ni][0] * alpha + bmlo;
            float v01 = acc[mi][ni][1] * alpha + bmlo;
            float v10 = acc[mi][ni][2] * alpha + bmhi;
            float v11 = acc[mi][ni][3] * alpha + bmhi;
            if (HAS_EXP) {
                v00 = __expf(v00 + wlo + u0); v01 = __expf(v01 + wlo + u1);
                v10 = __expf(v10 + whi + u0); v11 = __expf(v11 + whi + u1);
                slo += v00 + v01;
                shi += v10 + v11;
            }
            if (HAS_RSC) {
                v00 *= rlo; v01 *= rlo;
                v10 *= rhi; v11 *= rhi;
            }
            long long olo = (long long)mlo * N + col;
            long long ohi = (long long)mhi * N + col;
            if (HAS_RES) {
                float2 r0 = *reinterpret_cast<const float2*>(&Rp[olo]);
                float2 r1 = *reinterpret_cast<const float2*>(&Rp[ohi]);
                v00 += r0.x; v01 += r0.y; v10 += r1.x; v11 += r1.y;
            }
            if (OUT_BF16) {
                __nv_bfloat162 plo(__float2bfloat16_rn(v00), __float2bfloat16_rn(v01));
                __nv_bfloat162 phi(__float2bfloat16_rn(v10), __float2bfloat16_rn(v11));
                *reinterpret_cast<__nv_bfloat162*>(&Ch[olo]) = plo;
                *reinterpret_cast<__nv_bfloat162*>(&Ch[ohi]) = phi;
            } else {
                *reinterpret_cast<float2*>(&Cf[olo]) = make_float2(v00, v01);
                *reinterpret_cast<float2*>(&Cf[ohi]) = make_float2(v10, v11);
            }
        }
        if (HAS_EXP) {
            slo += __shfl_xor_sync(0xffffffffu, slo, 1);
            slo += __shfl_xor_sync(0xffffffffu, slo, 2);
            shi += __shfl_xor_sync(0xffffffffu, shi, 1);
            shi += __shfl_xor_sync(0xffffffffu, shi, 2);
            if (t == 0) {
                atomicAdd(&So[mlo], slo);
                atomicAdd(&So[mhi], shi);
            }
        }
    }
}

// ---------------------------------------------------------------------------
// Launch (PDL chain)
// ---------------------------------------------------------------------------
extern "C" void kernel_launch(void* const* d_in, const int* in_sizes, int n_in,
                              void* d_out, int out_size)
{
    const float* x     = (const float*)d_in[0];
    const float* gamma = (const float*)d_in[1];
    const float* beta  = (const float*)d_in[2];
    const float* wq    = (const float*)d_in[3];
    const float* bq    = (const float*)d_in[4];
    const float* wk    = (const float*)d_in[5];
    const float* bk    = (const float*)d_in[6];
    const float* wv    = (const float*)d_in[7];
    const float* bv    = (const float*)d_in[8];
    const float* wp    = (const float*)d_in[9];
    const float* bp    = (const float*)d_in[10];
    float* out = (float*)d_out;

    __nv_bfloat16 *xnt, *yt, *v, *at, *ot, *bwp, *bwqt, *bwkt, *bm;
    float* fbuf;
    cudaGetSymbolAddress((void**)&xnt,  g_xnt);
    cudaGetSymbolAddress((void**)&yt,   g_yt);
    cudaGetSymbolAddress((void**)&v,    g_v);
    cudaGetSymbolAddress((void**)&at,   g_at);
    cudaGetSymbolAddress((void**)&ot,   g_ot);
    cudaGetSymbolAddress((void**)&bwp,  g_wp);
    cudaGetSymbolAddress((void**)&bwqt, g_wqt);
    cudaGetSymbolAddress((void**)&bwkt, g_wkt);
    cudaGetSymbolAddress((void**)&bm,   g_m);
    cudaGetSymbolAddress((void**)&fbuf, g_f);

    float* rsum = fbuf + OFF_RS;
    float* wv_f = fbuf + OFF_W;
    float* uv_f = fbuf + OFF_U;
    float* c0p  = fbuf + OFF_C0;

    const long long sSC = (long long)HW_ * C_;
    const long long sHH = (long long)HW_ * HW_;
    const float scale = 1.0f / sqrtf((float)C_);

    cudaFuncSetAttribute(gn_t_kernel,
                         cudaFuncAttributeMaxDynamicSharedMemorySize, GN_SMEM);
    cudaFuncSetAttribute(yv_gemm,
                         cudaFuncAttributeMaxDynamicSharedMemorySize, SMEM_BYTES);
    cudaFuncSetAttribute(bf_gemm<0, false, true, false, false, false>,
                         cudaFuncAttributeMaxDynamicSharedMemorySize, SMEM_BYTES);
    cudaFuncSetAttribute(bf_gemm<0, false, true, true, false, true>,
                         cudaFuncAttributeMaxDynamicSharedMemorySize, SMEM_BYTES);
    cudaFuncSetAttribute(bf_gemm<0, false, true, false, true, false>,
                         cudaFuncAttributeMaxDynamicSharedMemorySize, SMEM_BYTES);
    cudaFuncSetAttribute(bf_gemm<1, true, false, false, false, false>,
                         cudaFuncAttributeMaxDynamicSharedMemorySize, SMEM_BYTES);

    cudaLaunchAttribute pdl[1];
    pdl[0].id = cudaLaunchAttributeProgrammaticStreamSerialization;
    pdl[0].val.programmaticStreamSerializationAllowed = 1;

    // 0) zero accumulators (rsum, w, u, pvec, qvec, c0)
    cudaMemsetAsync(fbuf, 0, sizeof(float) * 50184);

    // 1) prep: weight conversion + transposes + bias vectors
    {
        cudaLaunchConfig_t cfg = {};
        cfg.gridDim = dim3(641); cfg.blockDim = dim3(512);
        cfg.attrs = pdl; cfg.numAttrs = 1;
        cudaLaunchKernelEx(&cfg, prep_kernel, wq, wk, wv, wp, bq, bk);
    }

    // 2) M[c,c'] = sum_o Wq[o,c] Wk[o,c']  (A=wq_t, B=wk_t)
    {
        cudaLaunchConfig_t cfg = {};
        cfg.gridDim = dim3(C_ / 128, C_ / 128, 1); cfg.blockDim = dim3(256);
        cfg.dynamicSmemBytes = SMEM_BYTES; cfg.attrs = pdl; cfg.numAttrs = 1;
        cudaLaunchKernelEx(&cfg, bf_gemm<0, false, true, false, false, false>,
                           (const __nv_bfloat16*)bwqt, (const __nv_bfloat16*)bwkt,
                           (void*)bm, (const float*)nullptr, (const float*)nullptr,
                           (const float*)nullptr, (float*)nullptr,
                           (const float*)nullptr, (const float*)nullptr,
                           (const float*)nullptr,
                           C_, C_, C_, C_, 1.0f, 0LL, 0LL, 0LL, 0LL);
    }

    // 3) GroupNorm + transpose + w/u accumulation
    {
        cudaLaunchConfig_t cfg = {};
        cfg.gridDim = dim3(B_ * NG_); cfg.blockDim = dim3(512);
        cfg.dynamicSmemBytes = GN_SMEM; cfg.attrs = pdl; cfg.numAttrs = 1;
        cudaLaunchKernelEx(&cfg, gn_t_kernel, x, gamma, beta);
    }

    // 4) fused y / v
    {
        cudaLaunchConfig_t cfg = {};
        cfg.gridDim = dim3(32, 1, 32); cfg.blockDim = dim3(256);
        cfg.dynamicSmemBytes = SMEM_BYTES; cfg.attrs = pdl; cfg.numAttrs = 1;
        cudaLaunchKernelEx(&cfg, yv_gemm, bv);
    }

    // 5) at = exp(scale*(xn . y) + scale*(w+u+c0)) + atomic rowsums
    {
        cudaLaunchConfig_t cfg = {};
        cfg.gridDim = dim3(HW_ / 128, HW_ / 128, B_); cfg.blockDim = dim3(256);
        cfg.dynamicSmemBytes = SMEM_BYTES; cfg.attrs = pdl; cfg.numAttrs = 1;
        cudaLaunchKernelEx(&cfg, bf_gemm<0, false, true, true, false, true>,
                           (const __nv_bfloat16*)xnt, (const __nv_bfloat16*)yt,
                           (void*)at, (const float*)nullptr, (const float*)nullptr,
                           (const float*)nullptr, rsum,
                           (const float*)wv_f, (const float*)uv_f,
                           (const float*)c0p,
                           C_, C_, C_, HW_, scale, sSC, sSC, sHH, (long long)HW_);
    }

    // 6) ot = (at . v) / rowsum
    {
        cudaLaunchConfig_t cfg = {};
        cfg.gridDim = dim3(C_ / 128, HW_ / 128, B_); cfg.blockDim = dim3(256);
        cfg.dynamicSmemBytes = SMEM_BYTES; cfg.attrs = pdl; cfg.numAttrs = 1;
        cudaLaunchKernelEx(&cfg, bf_gemm<0, false, true, false, true, false>,
                           (const __nv_bfloat16*)at, (const __nv_bfloat16*)v,
                           (void*)ot, (const float*)nullptr, (const float*)nullptr,
                           (const float*)rsum, (float*)nullptr,
                           (const float*)nullptr, (const float*)nullptr,
                           (const float*)nullptr,
                           HW_, HW_, HW_, C_, 1.0f, sHH, sSC, sSC, (long long)HW_);
    }

    // 7) out = wp . ot + bp + x
    {
        cudaLaunchConfig_t cfg = {};
        cfg.gridDim = dim3(HW_ / 128, C_ / 128, B_); cfg.blockDim = dim3(256);
        cfg.dynamicSmemBytes = SMEM_BYTES; cfg.attrs = pdl; cfg.numAttrs = 1;
        cudaLaunchKernelEx(&cfg, bf_gemm<1, true, false, false, false, false>,
                           (const __nv_bfloat16*)bwp, (const __nv_bfloat16*)ot,
                           (void*)out, bp, x,
                           (const float*)nullptr, (float*)nullptr,
                           (const float*)nullptr, (const float*)nullptr,
                           (const float*)nullptr,
                           C_, C_, C_, HW_, 1.0f, 0LL, sSC, sSC, 0LL);
    }
}